// round 1
// baseline (speedup 1.0000x reference)
#include <cuda_runtime.h>
#include <cstdint>

#define N_NODES 8192
#define N_EDGES 262144
#define N_INPUT 3000
#define ENC1 128
#define ENC2 256
#define N_Z 20
#define SLOPE 0.2f

// -------- scratch (no allocations allowed) --------
__device__ float g_s1[N_NODES * ENC1];   // leaky(x@w1)
__device__ float g_s2[N_NODES * ENC2];   // leaky(z1@w2)
__device__ float g_s3[N_NODES * N_Z];    // z2@w3

// ============================================================
// Tiled fp32 GEMM: C[M,N] = (optional leaky)(A[M,K] @ B[K,N])
// 64x64 tile, 256 threads, 4x4 per thread, BK=16
// Requires M%64==0, N%64==0, K%4==0.
// ============================================================
__global__ __launch_bounds__(256) void gemm64(
    const float* __restrict__ A, const float* __restrict__ B,
    float* __restrict__ C, int M, int N, int K, int leaky)
{
    __shared__ float As[16][64];      // [k][m]
    __shared__ float Bs[16][68];      // [k][n] (+4 pad)

    int tid = threadIdx.x;
    int bm = blockIdx.y * 64;
    int bn = blockIdx.x * 64;
    int tx = tid & 15;        // n-group
    int ty = tid >> 4;        // m-group

    float acc[4][4];
#pragma unroll
    for (int i = 0; i < 4; i++)
#pragma unroll
        for (int j = 0; j < 4; j++) acc[i][j] = 0.f;

    // A loader: thread -> (row = tid/4, kq = (tid&3)*4)
    int a_row = tid >> 2;
    int a_k   = (tid & 3) * 4;
    // B loader: thread -> (k = tid/16, n = (tid&15)*4)
    int b_k = tid >> 4;
    int b_n = (tid & 15) * 4;

    for (int k0 = 0; k0 < K; k0 += 16) {
        // ---- load A tile (64x16) ----
        {
            int gk = k0 + a_k;
            size_t base = (size_t)(bm + a_row) * K;
            float4 av;
            if (gk + 3 < K) {
                av = *reinterpret_cast<const float4*>(&A[base + gk]);
            } else {
                av.x = (gk + 0 < K) ? A[base + gk + 0] : 0.f;
                av.y = (gk + 1 < K) ? A[base + gk + 1] : 0.f;
                av.z = (gk + 2 < K) ? A[base + gk + 2] : 0.f;
                av.w = (gk + 3 < K) ? A[base + gk + 3] : 0.f;
            }
            As[a_k + 0][a_row] = av.x;
            As[a_k + 1][a_row] = av.y;
            As[a_k + 2][a_row] = av.z;
            As[a_k + 3][a_row] = av.w;
        }
        // ---- load B tile (16x64) ----
        {
            int gbk = k0 + b_k;
            float4 bv = make_float4(0.f, 0.f, 0.f, 0.f);
            if (gbk < K)
                bv = *reinterpret_cast<const float4*>(&B[(size_t)gbk * N + bn + b_n]);
            *reinterpret_cast<float4*>(&Bs[b_k][b_n]) = bv;
        }
        __syncthreads();

#pragma unroll
        for (int k = 0; k < 16; k++) {
            float4 ra = *reinterpret_cast<const float4*>(&As[k][ty * 4]);
            float4 rb = *reinterpret_cast<const float4*>(&Bs[k][tx * 4]);
            float a0 = ra.x, a1 = ra.y, a2 = ra.z, a3 = ra.w;
            float b0 = rb.x, b1 = rb.y, b2 = rb.z, b3 = rb.w;
            acc[0][0] += a0 * b0; acc[0][1] += a0 * b1; acc[0][2] += a0 * b2; acc[0][3] += a0 * b3;
            acc[1][0] += a1 * b0; acc[1][1] += a1 * b1; acc[1][2] += a1 * b2; acc[1][3] += a1 * b3;
            acc[2][0] += a2 * b0; acc[2][1] += a2 * b1; acc[2][2] += a2 * b2; acc[2][3] += a2 * b3;
            acc[3][0] += a3 * b0; acc[3][1] += a3 * b1; acc[3][2] += a3 * b2; acc[3][3] += a3 * b3;
        }
        __syncthreads();
    }

#pragma unroll
    for (int i = 0; i < 4; i++) {
        int m = bm + ty * 4 + i;
        float4 o;
        o.x = acc[i][0]; o.y = acc[i][1]; o.z = acc[i][2]; o.w = acc[i][3];
        if (leaky) {
            o.x = (o.x >= 0.f) ? o.x : SLOPE * o.x;
            o.y = (o.y >= 0.f) ? o.y : SLOPE * o.y;
            o.z = (o.z >= 0.f) ? o.z : SLOPE * o.z;
            o.w = (o.w >= 0.f) ? o.w : SLOPE * o.w;
        }
        *reinterpret_cast<float4*>(&C[(size_t)m * N + bn + tx * 4]) = o;
    }
}

// ============================================================
// Small GEMM: C[8192,20] = A[8192,256] @ B[256,20]   (no leaky)
// block = 320 threads = 16 rows x 20 cols; shared B.
// ============================================================
__global__ __launch_bounds__(320) void gemm_w3(
    const float* __restrict__ A, const float* __restrict__ B,
    float* __restrict__ C)
{
    __shared__ float Bs[256 * 20];
    int tid = threadIdx.x;
    for (int i = tid; i < 256 * 20; i += 320) Bs[i] = B[i];
    __syncthreads();

    int ty = tid / 20;      // local row 0..15
    int n  = tid % 20;
    int m = blockIdx.x * 16 + ty;

    const float* arow = A + (size_t)m * 256;
    float acc = 0.f;
#pragma unroll 8
    for (int k = 0; k < 256; k++)
        acc += arow[k] * Bs[k * 20 + n];
    C[(size_t)m * 20 + n] = acc;
}

// ============================================================
// SpMM: out[r] += v * feat[c] for every edge; float4 per thread.
// Caller zeroes out first. D4 = D/4.
// ============================================================
__global__ __launch_bounds__(256) void spmm_kernel(
    const int* __restrict__ rows, const int* __restrict__ cols,
    const float* __restrict__ vals, const float* __restrict__ feat,
    float* __restrict__ out, int D4)
{
    long idx = (long)blockIdx.x * blockDim.x + threadIdx.x;
    long total = (long)N_EDGES * D4;
    if (idx >= total) return;
    int e  = (int)(idx / D4);
    int c4 = (int)(idx % D4);
    int r = rows[e];
    int c = cols[e];
    float v = vals[e];
    float4 fv = reinterpret_cast<const float4*>(feat)[(long)c * D4 + c4];
    float* o = out + ((long)r * D4 + c4) * 4;
    atomicAdd(o + 0, v * fv.x);
    atomicAdd(o + 1, v * fv.y);
    atomicAdd(o + 2, v * fv.z);
    atomicAdd(o + 3, v * fv.w);
}

// ============================================================
// Decoder: out[i][j] = sigmoid(dot(Z[i], Z[j])), Z = [8192, 20]
// 64x64 tile, 256 threads, 4x4 per thread.
// ============================================================
__global__ __launch_bounds__(256) void decoder_kernel(
    const float* __restrict__ Z, float* __restrict__ out)
{
    __shared__ float Zr[64][21];
    __shared__ float Zc[64][21];
    int tid = threadIdx.x;
    int bm = blockIdx.y * 64;
    int bn = blockIdx.x * 64;

    for (int i = tid; i < 64 * 20; i += 256) {
        int r = i / 20, c = i % 20;
        Zr[r][c] = Z[(size_t)(bm + r) * 20 + c];
        Zc[r][c] = Z[(size_t)(bn + r) * 20 + c];
    }
    __syncthreads();

    int tx = tid & 15;
    int ty = tid >> 4;
    float acc[4][4];
#pragma unroll
    for (int i = 0; i < 4; i++)
#pragma unroll
        for (int j = 0; j < 4; j++) acc[i][j] = 0.f;

#pragma unroll
    for (int k = 0; k < 20; k++) {
        float ra[4], rb[4];
#pragma unroll
        for (int i = 0; i < 4; i++) ra[i] = Zr[ty * 4 + i][k];
#pragma unroll
        for (int j = 0; j < 4; j++) rb[j] = Zc[tx * 4 + j][k];
#pragma unroll
        for (int i = 0; i < 4; i++)
#pragma unroll
            for (int j = 0; j < 4; j++)
                acc[i][j] += ra[i] * rb[j];
    }

#pragma unroll
    for (int i = 0; i < 4; i++) {
        int m = bm + ty * 4 + i;
        float4 o;
        o.x = 1.f / (1.f + expf(-acc[i][0]));
        o.y = 1.f / (1.f + expf(-acc[i][1]));
        o.z = 1.f / (1.f + expf(-acc[i][2]));
        o.w = 1.f / (1.f + expf(-acc[i][3]));
        *reinterpret_cast<float4*>(&out[(size_t)m * N_NODES + bn + tx * 4]) = o;
    }
}

// ============================================================
// Launch
// ============================================================
extern "C" void kernel_launch(void* const* d_in, const int* in_sizes, int n_in,
                              void* d_out, int out_size)
{
    const float* x        = (const float*)d_in[0];
    const int*   adj_rows = (const int*)  d_in[1];
    const int*   adj_cols = (const int*)  d_in[2];
    const float* adj_vals = (const float*)d_in[3];
    const float* w1       = (const float*)d_in[4];
    const float* w2       = (const float*)d_in[5];
    const float* w3       = (const float*)d_in[6];
    float* out = (float*)d_out;

    // output layout (floats)
    float* z_igae = out;                                   // [8192, 20]
    float* adj    = z_igae + (size_t)N_NODES * N_Z;        // [8192, 8192]
    float* az1    = adj    + (size_t)N_NODES * N_NODES;    // [8192, 128]
    float* az2    = az1    + (size_t)N_NODES * ENC1;       // [8192, 256]
    float* az3    = az2    + (size_t)N_NODES * ENC2;       // [8192, 20]
    float* z1     = az3    + (size_t)N_NODES * N_Z;        // [8192, 128]
    float* z2     = z1     + (size_t)N_NODES * ENC1;       // [8192, 256]

    float *s1, *s2, *s3;
    cudaGetSymbolAddress((void**)&s1, g_s1);
    cudaGetSymbolAddress((void**)&s2, g_s2);
    cudaGetSymbolAddress((void**)&s3, g_s3);

    cudaStream_t st = 0;

    // ---- layer 1 ----
    {
        dim3 grid(ENC1 / 64, N_NODES / 64);
        gemm64<<<grid, 256, 0, st>>>(x, w1, s1, N_NODES, ENC1, N_INPUT, 1);
    }
    cudaMemsetAsync(z1, 0, (size_t)N_NODES * ENC1 * sizeof(float), st);
    {
        long total = (long)N_EDGES * (ENC1 / 4);
        spmm_kernel<<<(unsigned)((total + 255) / 256), 256, 0, st>>>(
            adj_rows, adj_cols, adj_vals, s1, z1, ENC1 / 4);
    }
    cudaMemsetAsync(az1, 0, (size_t)N_NODES * ENC1 * sizeof(float), st);
    {
        long total = (long)N_EDGES * (ENC1 / 4);
        spmm_kernel<<<(unsigned)((total + 255) / 256), 256, 0, st>>>(
            adj_rows, adj_cols, adj_vals, z1, az1, ENC1 / 4);
    }

    // ---- layer 2 ----
    {
        dim3 grid(ENC2 / 64, N_NODES / 64);
        gemm64<<<grid, 256, 0, st>>>(z1, w2, s2, N_NODES, ENC2, ENC1, 1);
    }
    cudaMemsetAsync(z2, 0, (size_t)N_NODES * ENC2 * sizeof(float), st);
    {
        long total = (long)N_EDGES * (ENC2 / 4);
        spmm_kernel<<<(unsigned)((total + 255) / 256), 256, 0, st>>>(
            adj_rows, adj_cols, adj_vals, s2, z2, ENC2 / 4);
    }
    cudaMemsetAsync(az2, 0, (size_t)N_NODES * ENC2 * sizeof(float), st);
    {
        long total = (long)N_EDGES * (ENC2 / 4);
        spmm_kernel<<<(unsigned)((total + 255) / 256), 256, 0, st>>>(
            adj_rows, adj_cols, adj_vals, z2, az2, ENC2 / 4);
    }

    // ---- layer 3 (no activation) ----
    gemm_w3<<<N_NODES / 16, 320, 0, st>>>(z2, w3, s3);

    cudaMemsetAsync(z_igae, 0, (size_t)N_NODES * N_Z * sizeof(float), st);
    {
        long total = (long)N_EDGES * (N_Z / 4);
        spmm_kernel<<<(unsigned)((total + 255) / 256), 256, 0, st>>>(
            adj_rows, adj_cols, adj_vals, s3, z_igae, N_Z / 4);
    }
    cudaMemsetAsync(az3, 0, (size_t)N_NODES * N_Z * sizeof(float), st);
    {
        long total = (long)N_EDGES * (N_Z / 4);
        spmm_kernel<<<(unsigned)((total + 255) / 256), 256, 0, st>>>(
            adj_rows, adj_cols, adj_vals, z_igae, az3, N_Z / 4);
    }

    // ---- decoder ----
    {
        dim3 grid(N_NODES / 64, N_NODES / 64);
        decoder_kernel<<<grid, 256, 0, st>>>(z_igae, adj);
    }

    (void)in_sizes; (void)n_in; (void)out_size;
}

// round 2
// speedup vs baseline: 1.4414x; 1.4414x over previous
#include <cuda_runtime.h>
#include <cstdint>

#define N_NODES 8192
#define N_EDGES 262144
#define N_INPUT 3000
#define ENC1 128
#define ENC2 256
#define N_Z 20
#define SLOPE 0.2f

// -------- scratch (no runtime allocations allowed) --------
__device__ float g_s1[N_NODES * ENC1];   // leaky(x@w1)
__device__ float g_s2[N_NODES * ENC2];   // leaky(z1@w2)
__device__ float g_s3[N_NODES * N_Z];    // z2@w3
// CSR scratch
__device__ int   g_cnt[N_NODES + 1];
__device__ int   g_off[N_NODES + 1];
__device__ int   g_pos[N_NODES];
__device__ int   g_ecol[N_EDGES];
__device__ float g_eval[N_EDGES];

// ============================================================
// CSR build: count -> scan -> scatter
// ============================================================
__global__ __launch_bounds__(1024) void count_kernel(const int* __restrict__ rows,
                                                     int* __restrict__ cnt)
{
    int e = blockIdx.x * 1024 + threadIdx.x;
    if (e < N_EDGES) atomicAdd(&cnt[rows[e]], 1);
}

__global__ __launch_bounds__(1024) void scan_kernel(const int* __restrict__ cnt,
                                                    int* __restrict__ off,
                                                    int* __restrict__ pos)
{
    __shared__ int wsum[32];
    int tid = threadIdx.x;
    int base = tid * 8;
    int v[8];
    int s = 0;
#pragma unroll
    for (int i = 0; i < 8; i++) { v[i] = cnt[base + i]; s += v[i]; }
    int lane = tid & 31, warp = tid >> 5;
    // inclusive warp scan of thread sums
    int inc = s;
#pragma unroll
    for (int d = 1; d < 32; d <<= 1) {
        int t = __shfl_up_sync(0xffffffff, inc, d);
        if (lane >= d) inc += t;
    }
    if (lane == 31) wsum[warp] = inc;
    __syncthreads();
    if (warp == 0) {
        int w = wsum[lane];
        int wi = w;
#pragma unroll
        for (int d = 1; d < 32; d <<= 1) {
            int t = __shfl_up_sync(0xffffffff, wi, d);
            if (lane >= d) wi += t;
        }
        wsum[lane] = wi - w;   // exclusive
    }
    __syncthreads();
    int run = wsum[warp] + (inc - s);  // exclusive prefix for this thread
#pragma unroll
    for (int i = 0; i < 8; i++) {
        off[base + i] = run;
        pos[base + i] = run;
        run += v[i];
    }
    if (tid == 1023) off[N_NODES] = run;
}

__global__ __launch_bounds__(1024) void scatter_kernel(
    const int* __restrict__ rows, const int* __restrict__ cols,
    const float* __restrict__ vals, int* __restrict__ pos,
    int* __restrict__ ecol, float* __restrict__ eval)
{
    int e = blockIdx.x * 1024 + threadIdx.x;
    if (e >= N_EDGES) return;
    int r = rows[e];
    int idx = atomicAdd(&pos[r], 1);
    ecol[idx] = cols[e];
    eval[idx] = vals[e];
}

// ============================================================
// CSR SpMM: one CTA per node, D threads, register accumulate.
// ============================================================
template <int D>
__global__ __launch_bounds__(D) void spmm_csr(
    const int* __restrict__ off, const int* __restrict__ ecol,
    const float* __restrict__ eval, const float* __restrict__ feat,
    float* __restrict__ out)
{
    int node = blockIdx.x;
    int tid = threadIdx.x;
    int s = off[node], e = off[node + 1];
    float acc = 0.f;
    int i = s;
    for (; i + 4 <= e; i += 4) {
        int c0 = ecol[i], c1 = ecol[i + 1], c2 = ecol[i + 2], c3 = ecol[i + 3];
        float v0 = eval[i], v1 = eval[i + 1], v2 = eval[i + 2], v3 = eval[i + 3];
        float f0 = feat[(size_t)c0 * D + tid];
        float f1 = feat[(size_t)c1 * D + tid];
        float f2 = feat[(size_t)c2 * D + tid];
        float f3 = feat[(size_t)c3 * D + tid];
        acc += v0 * f0; acc += v1 * f1; acc += v2 * f2; acc += v3 * f3;
    }
    for (; i < e; i++) acc += eval[i] * feat[(size_t)ecol[i] * D + tid];
    out[(size_t)node * D + tid] = acc;
}

// D=20 variant: one warp per node (lanes 0..19 active)
__global__ __launch_bounds__(256) void spmm_csr20(
    const int* __restrict__ off, const int* __restrict__ ecol,
    const float* __restrict__ eval, const float* __restrict__ feat,
    float* __restrict__ out)
{
    int warp = (blockIdx.x * 256 + threadIdx.x) >> 5;
    int lane = threadIdx.x & 31;
    if (warp >= N_NODES || lane >= N_Z) return;
    int s = off[warp], e = off[warp + 1];
    float acc = 0.f;
    int i = s;
    for (; i + 2 <= e; i += 2) {
        int c0 = ecol[i], c1 = ecol[i + 1];
        float v0 = eval[i], v1 = eval[i + 1];
        acc += v0 * feat[(size_t)c0 * N_Z + lane];
        acc += v1 * feat[(size_t)c1 * N_Z + lane];
    }
    for (; i < e; i++) acc += eval[i] * feat[(size_t)ecol[i] * N_Z + lane];
    out[(size_t)warp * N_Z + lane] = acc;
}

// ============================================================
// fp32 GEMM: C = (opt leaky)(A[M,K] @ B[K,N])
// BM=64 BN=64 BK=16, 128 threads, 8x4 per thread.
// Requires M%64==0, N%64==0, K%4==0.
// ============================================================
__global__ __launch_bounds__(128) void gemm_tile(
    const float* __restrict__ A, const float* __restrict__ B,
    float* __restrict__ C, int M, int N, int K, int leaky)
{
    __shared__ float As[16][64];
    __shared__ float Bs[16][68];

    int tid = threadIdx.x;
    int bm = blockIdx.y * 64;
    int bn = blockIdx.x * 64;
    int tx = tid & 15;     // col group (4 cols)
    int ty = tid >> 4;     // row group (8 rows)

    float acc[8][4];
#pragma unroll
    for (int i = 0; i < 8; i++)
#pragma unroll
        for (int j = 0; j < 4; j++) acc[i][j] = 0.f;

    int KT = (K + 15) / 16;
    for (int t = 0; t < KT; t++) {
        int k0 = t * 16;
        // ---- A tile: 64x16, 256 vec4, 2 per thread ----
#pragma unroll
        for (int l = 0; l < 2; l++) {
            int lin = tid + l * 128;
            int row = lin >> 2;
            int kq = (lin & 3) * 4;
            int gk = k0 + kq;
            float4 av = make_float4(0.f, 0.f, 0.f, 0.f);
            if (gk < K)  // K%4==0 so full vec4 is in-bounds
                av = *reinterpret_cast<const float4*>(&A[(size_t)(bm + row) * K + gk]);
            As[kq + 0][row] = av.x;
            As[kq + 1][row] = av.y;
            As[kq + 2][row] = av.z;
            As[kq + 3][row] = av.w;
        }
        // ---- B tile: 16x64, 256 vec4, 2 per thread ----
#pragma unroll
        for (int l = 0; l < 2; l++) {
            int lin = tid + l * 128;
            int k = lin >> 4;
            int n = (lin & 15) * 4;
            int gk = k0 + k;
            float4 bv = make_float4(0.f, 0.f, 0.f, 0.f);
            if (gk < K)
                bv = *reinterpret_cast<const float4*>(&B[(size_t)gk * N + bn + n]);
            *reinterpret_cast<float4*>(&Bs[k][n]) = bv;
        }
        __syncthreads();

#pragma unroll
        for (int k = 0; k < 16; k++) {
            float4 a0 = *reinterpret_cast<const float4*>(&As[k][ty * 8]);
            float4 a1 = *reinterpret_cast<const float4*>(&As[k][ty * 8 + 4]);
            float4 b  = *reinterpret_cast<const float4*>(&Bs[k][tx * 4]);
            float a[8] = {a0.x, a0.y, a0.z, a0.w, a1.x, a1.y, a1.z, a1.w};
            float bb[4] = {b.x, b.y, b.z, b.w};
#pragma unroll
            for (int i = 0; i < 8; i++)
#pragma unroll
                for (int j = 0; j < 4; j++)
                    acc[i][j] += a[i] * bb[j];
        }
        __syncthreads();
    }

#pragma unroll
    for (int i = 0; i < 8; i++) {
        int m = bm + ty * 8 + i;
        float4 o;
        o.x = acc[i][0]; o.y = acc[i][1]; o.z = acc[i][2]; o.w = acc[i][3];
        if (leaky) {
            o.x = (o.x >= 0.f) ? o.x : SLOPE * o.x;
            o.y = (o.y >= 0.f) ? o.y : SLOPE * o.y;
            o.z = (o.z >= 0.f) ? o.z : SLOPE * o.z;
            o.w = (o.w >= 0.f) ? o.w : SLOPE * o.w;
        }
        *reinterpret_cast<float4*>(&C[(size_t)m * N + bn + tx * 4]) = o;
    }
}

// ============================================================
// Small GEMM: C[8192,20] = A[8192,256] @ B[256,20]
// ============================================================
__global__ __launch_bounds__(320) void gemm_w3(
    const float* __restrict__ A, const float* __restrict__ B,
    float* __restrict__ C)
{
    __shared__ float Bs[256 * 20];
    int tid = threadIdx.x;
    for (int i = tid; i < 256 * 20; i += 320) Bs[i] = B[i];
    __syncthreads();

    int ty = tid / 20;
    int n  = tid % 20;
    int m = blockIdx.x * 16 + ty;

    const float* arow = A + (size_t)m * 256;
    float acc = 0.f;
#pragma unroll 8
    for (int k = 0; k < 256; k++)
        acc += arow[k] * Bs[k * 20 + n];
    C[(size_t)m * 20 + n] = acc;
}

// ============================================================
// Decoder: out[i][j] = sigmoid(dot(Z[i], Z[j])), Z=[8192,20]
// ============================================================
__global__ __launch_bounds__(256) void decoder_kernel(
    const float* __restrict__ Z, float* __restrict__ out)
{
    __shared__ float Zr[64][21];
    __shared__ float Zc[64][21];
    int tid = threadIdx.x;
    int bm = blockIdx.y * 64;
    int bn = blockIdx.x * 64;

    for (int i = tid; i < 64 * 20; i += 256) {
        int r = i / 20, c = i % 20;
        Zr[r][c] = Z[(size_t)(bm + r) * 20 + c];
        Zc[r][c] = Z[(size_t)(bn + r) * 20 + c];
    }
    __syncthreads();

    int tx = tid & 15;
    int ty = tid >> 4;
    float acc[4][4];
#pragma unroll
    for (int i = 0; i < 4; i++)
#pragma unroll
        for (int j = 0; j < 4; j++) acc[i][j] = 0.f;

#pragma unroll
    for (int k = 0; k < 20; k++) {
        float ra[4], rb[4];
#pragma unroll
        for (int i = 0; i < 4; i++) ra[i] = Zr[ty * 4 + i][k];
#pragma unroll
        for (int j = 0; j < 4; j++) rb[j] = Zc[tx * 4 + j][k];
#pragma unroll
        for (int i = 0; i < 4; i++)
#pragma unroll
            for (int j = 0; j < 4; j++)
                acc[i][j] += ra[i] * rb[j];
    }

#pragma unroll
    for (int i = 0; i < 4; i++) {
        int m = bm + ty * 4 + i;
        float4 o;
        o.x = 1.f / (1.f + __expf(-acc[i][0]));
        o.y = 1.f / (1.f + __expf(-acc[i][1]));
        o.z = 1.f / (1.f + __expf(-acc[i][2]));
        o.w = 1.f / (1.f + __expf(-acc[i][3]));
        *reinterpret_cast<float4*>(&out[(size_t)m * N_NODES + bn + tx * 4]) = o;
    }
}

// ============================================================
// Launch
// ============================================================
extern "C" void kernel_launch(void* const* d_in, const int* in_sizes, int n_in,
                              void* d_out, int out_size)
{
    const float* x        = (const float*)d_in[0];
    const int*   adj_rows = (const int*)  d_in[1];
    const int*   adj_cols = (const int*)  d_in[2];
    const float* adj_vals = (const float*)d_in[3];
    const float* w1       = (const float*)d_in[4];
    const float* w2       = (const float*)d_in[5];
    const float* w3       = (const float*)d_in[6];
    float* out = (float*)d_out;

    // output layout (floats)
    float* z_igae = out;                                   // [8192, 20]
    float* adj    = z_igae + (size_t)N_NODES * N_Z;        // [8192, 8192]
    float* az1    = adj    + (size_t)N_NODES * N_NODES;    // [8192, 128]
    float* az2    = az1    + (size_t)N_NODES * ENC1;       // [8192, 256]
    float* az3    = az2    + (size_t)N_NODES * ENC2;       // [8192, 20]
    float* z1     = az3    + (size_t)N_NODES * N_Z;        // [8192, 128]
    float* z2     = z1     + (size_t)N_NODES * ENC1;       // [8192, 256]

    float *s1, *s2, *s3, *eval;
    int *cnt, *off, *pos, *ecol;
    cudaGetSymbolAddress((void**)&s1, g_s1);
    cudaGetSymbolAddress((void**)&s2, g_s2);
    cudaGetSymbolAddress((void**)&s3, g_s3);
    cudaGetSymbolAddress((void**)&cnt, g_cnt);
    cudaGetSymbolAddress((void**)&off, g_off);
    cudaGetSymbolAddress((void**)&pos, g_pos);
    cudaGetSymbolAddress((void**)&ecol, g_ecol);
    cudaGetSymbolAddress((void**)&eval, g_eval);

    cudaStream_t st = 0;

    // ---- build CSR ----
    cudaMemsetAsync(cnt, 0, (N_NODES + 1) * sizeof(int), st);
    count_kernel<<<N_EDGES / 1024, 1024, 0, st>>>(adj_rows, cnt);
    scan_kernel<<<1, 1024, 0, st>>>(cnt, off, pos);
    scatter_kernel<<<N_EDGES / 1024, 1024, 0, st>>>(adj_rows, adj_cols, adj_vals,
                                                    pos, ecol, eval);

    // ---- layer 1 ----
    {
        dim3 grid(ENC1 / 64, N_NODES / 64);
        gemm_tile<<<grid, 128, 0, st>>>(x, w1, s1, N_NODES, ENC1, N_INPUT, 1);
    }
    spmm_csr<ENC1><<<N_NODES, ENC1, 0, st>>>(off, ecol, eval, s1, z1);
    spmm_csr<ENC1><<<N_NODES, ENC1, 0, st>>>(off, ecol, eval, z1, az1);

    // ---- layer 2 ----
    {
        dim3 grid(ENC2 / 64, N_NODES / 64);
        gemm_tile<<<grid, 128, 0, st>>>(z1, w2, s2, N_NODES, ENC2, ENC1, 1);
    }
    spmm_csr<ENC2><<<N_NODES, ENC2, 0, st>>>(off, ecol, eval, s2, z2);
    spmm_csr<ENC2><<<N_NODES, ENC2, 0, st>>>(off, ecol, eval, z2, az2);

    // ---- layer 3 (no activation) ----
    gemm_w3<<<N_NODES / 16, 320, 0, st>>>(z2, w3, s3);
    spmm_csr20<<<N_NODES / 8, 256, 0, st>>>(off, ecol, eval, s3, z_igae);
    spmm_csr20<<<N_NODES / 8, 256, 0, st>>>(off, ecol, eval, z_igae, az3);

    // ---- decoder ----
    {
        dim3 grid(N_NODES / 64, N_NODES / 64);
        decoder_kernel<<<grid, 256, 0, st>>>(z_igae, adj);
    }

    (void)in_sizes; (void)n_in; (void)out_size;
}

// round 3
// speedup vs baseline: 1.9002x; 1.3183x over previous
#include <cuda_runtime.h>
#include <cuda_bf16.h>
#include <mma.h>
#include <cstdint>

using namespace nvcuda;

#define N_NODES 8192
#define N_EDGES 262144
#define N_INPUT 3000
#define ENC1 128
#define ENC2 256
#define N_Z 20
#define SLOPE 0.2f

// -------- scratch (no runtime allocations allowed) --------
__device__ float g_s1[N_NODES * ENC1];   // leaky(x@w1)
__device__ float g_s2[N_NODES * ENC2];   // leaky(z1@w2)
__device__ float g_s3[N_NODES * N_Z];    // z2@w3
// CSR scratch
__device__ int   g_cnt[N_NODES + 1];
__device__ int   g_off[N_NODES + 1];
__device__ int   g_pos[N_NODES];
__device__ int   g_ecol[N_EDGES];
__device__ float g_eval[N_EDGES];

// ============================================================
// CSR build: count -> scan -> scatter
// ============================================================
__global__ __launch_bounds__(1024) void count_kernel(const int* __restrict__ rows,
                                                     int* __restrict__ cnt)
{
    int e = blockIdx.x * 1024 + threadIdx.x;
    if (e < N_EDGES) atomicAdd(&cnt[rows[e]], 1);
}

__global__ __launch_bounds__(1024) void scan_kernel(const int* __restrict__ cnt,
                                                    int* __restrict__ off,
                                                    int* __restrict__ pos)
{
    __shared__ int wsum[32];
    int tid = threadIdx.x;
    int base = tid * 8;
    int v[8];
    int s = 0;
#pragma unroll
    for (int i = 0; i < 8; i++) { v[i] = cnt[base + i]; s += v[i]; }
    int lane = tid & 31, warp = tid >> 5;
    int inc = s;
#pragma unroll
    for (int d = 1; d < 32; d <<= 1) {
        int t = __shfl_up_sync(0xffffffff, inc, d);
        if (lane >= d) inc += t;
    }
    if (lane == 31) wsum[warp] = inc;
    __syncthreads();
    if (warp == 0) {
        int w = wsum[lane];
        int wi = w;
#pragma unroll
        for (int d = 1; d < 32; d <<= 1) {
            int t = __shfl_up_sync(0xffffffff, wi, d);
            if (lane >= d) wi += t;
        }
        wsum[lane] = wi - w;
    }
    __syncthreads();
    int run = wsum[warp] + (inc - s);
#pragma unroll
    for (int i = 0; i < 8; i++) {
        off[base + i] = run;
        pos[base + i] = run;
        run += v[i];
    }
    if (tid == 1023) off[N_NODES] = run;
}

__global__ __launch_bounds__(1024) void scatter_kernel(
    const int* __restrict__ rows, const int* __restrict__ cols,
    const float* __restrict__ vals, int* __restrict__ pos,
    int* __restrict__ ecol, float* __restrict__ eval)
{
    int e = blockIdx.x * 1024 + threadIdx.x;
    if (e >= N_EDGES) return;
    int r = rows[e];
    int idx = atomicAdd(&pos[r], 1);
    ecol[idx] = cols[e];
    eval[idx] = vals[e];
}

// ============================================================
// CSR SpMM: one CTA per node, D threads, register accumulate.
// ============================================================
template <int D>
__global__ __launch_bounds__(D) void spmm_csr(
    const int* __restrict__ off, const int* __restrict__ ecol,
    const float* __restrict__ eval, const float* __restrict__ feat,
    float* __restrict__ out)
{
    int node = blockIdx.x;
    int tid = threadIdx.x;
    int s = off[node], e = off[node + 1];
    float acc = 0.f;
    int i = s;
    for (; i + 4 <= e; i += 4) {
        int c0 = ecol[i], c1 = ecol[i + 1], c2 = ecol[i + 2], c3 = ecol[i + 3];
        float v0 = eval[i], v1 = eval[i + 1], v2 = eval[i + 2], v3 = eval[i + 3];
        float f0 = feat[(size_t)c0 * D + tid];
        float f1 = feat[(size_t)c1 * D + tid];
        float f2 = feat[(size_t)c2 * D + tid];
        float f3 = feat[(size_t)c3 * D + tid];
        acc += v0 * f0; acc += v1 * f1; acc += v2 * f2; acc += v3 * f3;
    }
    for (; i < e; i++) acc += eval[i] * feat[(size_t)ecol[i] * D + tid];
    out[(size_t)node * D + tid] = acc;
}

// D=20 variant: one warp per node (lanes 0..19 active)
__global__ __launch_bounds__(256) void spmm_csr20(
    const int* __restrict__ off, const int* __restrict__ ecol,
    const float* __restrict__ eval, const float* __restrict__ feat,
    float* __restrict__ out)
{
    int warp = (blockIdx.x * 256 + threadIdx.x) >> 5;
    int lane = threadIdx.x & 31;
    if (warp >= N_NODES || lane >= N_Z) return;
    int s = off[warp], e = off[warp + 1];
    float acc = 0.f;
    int i = s;
    for (; i + 2 <= e; i += 2) {
        int c0 = ecol[i], c1 = ecol[i + 1];
        float v0 = eval[i], v1 = eval[i + 1];
        acc += v0 * feat[(size_t)c0 * N_Z + lane];
        acc += v1 * feat[(size_t)c1 * N_Z + lane];
    }
    for (; i < e; i++) acc += eval[i] * feat[(size_t)ecol[i] * N_Z + lane];
    out[(size_t)warp * N_Z + lane] = acc;
}

// ============================================================
// Tensor-core GEMM with fused fp32 -> bf16 (hi,lo) split.
// C[M,N] = (opt leaky)(A[M,K] @ B[K,N]), fp32 in/out.
// acc += Ahi*Bhi + Ahi*Blo + Alo*Bhi  (error ~2^-17)
// BM=128, BN=64, BK=32; 256 threads (8 warps as 4x2, 32x32/warp).
// Requires M%128==0, N%64==0, K%4==0.
// ============================================================
#define GBM 128
#define GBN 64
#define GBK 32
#define LDA 40   // 32 + 8 pad (bf16) -> conflict-free ldmatrix
#define LDB 72   // 64 + 8 pad

__global__ __launch_bounds__(256) void gemm_tc(
    const float* __restrict__ A, const float* __restrict__ B,
    float* __restrict__ C, int M, int N, int K, int leaky)
{
    __shared__ __nv_bfloat16 sAhi[GBM][LDA];
    __shared__ __nv_bfloat16 sAlo[GBM][LDA];
    __shared__ __nv_bfloat16 sBhi[GBK][LDB];
    __shared__ __nv_bfloat16 sBlo[GBK][LDB];

    const int tid = threadIdx.x;
    const int bm = blockIdx.y * GBM;
    const int bn = blockIdx.x * GBN;
    const int wid = tid >> 5;
    const int wm = (wid & 3) * 32;   // warp row offset
    const int wn = (wid >> 2) * 32;  // warp col offset

    wmma::fragment<wmma::accumulator, 16, 16, 16, float> acc[2][2];
#pragma unroll
    for (int i = 0; i < 2; i++)
#pragma unroll
        for (int j = 0; j < 2; j++) wmma::fill_fragment(acc[i][j], 0.f);

    const int KT = (K + GBK - 1) / GBK;

    float4 ra[4], rb[2];

    // ---- global load helpers (zero-fill past K) ----
    auto loadA = [&](int t) {
        int k0 = t * GBK;
#pragma unroll
        for (int l = 0; l < 4; l++) {
            int lin = tid + l * 256;          // 0..1023
            int row = lin >> 3;               // 8 float4 per 32-col row
            int c4  = (lin & 7) * 4;
            int gk = k0 + c4;
            float4 v = make_float4(0.f, 0.f, 0.f, 0.f);
            if (gk < K)                        // K%4==0 -> full vec in-bounds
                v = *reinterpret_cast<const float4*>(&A[(size_t)(bm + row) * K + gk]);
            ra[l] = v;
        }
    };
    auto loadB = [&](int t) {
        int k0 = t * GBK;
#pragma unroll
        for (int l = 0; l < 2; l++) {
            int lin = tid + l * 256;          // 0..511
            int krow = lin >> 4;              // 16 float4 per 64-col row
            int c4 = (lin & 15) * 4;
            int gk = k0 + krow;
            float4 v = make_float4(0.f, 0.f, 0.f, 0.f);
            if (gk < K)
                v = *reinterpret_cast<const float4*>(&B[(size_t)gk * N + bn + c4]);
            rb[l] = v;
        }
    };
    auto store_tiles = [&]() {
#pragma unroll
        for (int l = 0; l < 4; l++) {
            int lin = tid + l * 256;
            int row = lin >> 3;
            int c4  = (lin & 7) * 4;
            float vv[4] = {ra[l].x, ra[l].y, ra[l].z, ra[l].w};
#pragma unroll
            for (int e = 0; e < 4; e++) {
                float v = vv[e];
                __nv_bfloat16 h = __float2bfloat16(v);
                __nv_bfloat16 lo = __float2bfloat16(v - __bfloat162float(h));
                sAhi[row][c4 + e] = h;
                sAlo[row][c4 + e] = lo;
            }
        }
#pragma unroll
        for (int l = 0; l < 2; l++) {
            int lin = tid + l * 256;
            int krow = lin >> 4;
            int c4 = (lin & 15) * 4;
            float vv[4] = {rb[l].x, rb[l].y, rb[l].z, rb[l].w};
#pragma unroll
            for (int e = 0; e < 4; e++) {
                float v = vv[e];
                __nv_bfloat16 h = __float2bfloat16(v);
                __nv_bfloat16 lo = __float2bfloat16(v - __bfloat162float(h));
                sBhi[krow][c4 + e] = h;
                sBlo[krow][c4 + e] = lo;
            }
        }
    };

    loadA(0); loadB(0);
    store_tiles();
    __syncthreads();

    for (int t = 0; t < KT; t++) {
        if (t + 1 < KT) { loadA(t + 1); loadB(t + 1); }  // LDG overlaps MMA

#pragma unroll
        for (int kk = 0; kk < GBK; kk += 16) {
            wmma::fragment<wmma::matrix_a, 16, 16, 16, __nv_bfloat16, wmma::row_major> ah[2], al[2];
            wmma::fragment<wmma::matrix_b, 16, 16, 16, __nv_bfloat16, wmma::row_major> bh[2], bl[2];
#pragma unroll
            for (int i = 0; i < 2; i++) {
                wmma::load_matrix_sync(ah[i], &sAhi[wm + 16 * i][kk], LDA);
                wmma::load_matrix_sync(al[i], &sAlo[wm + 16 * i][kk], LDA);
            }
#pragma unroll
            for (int j = 0; j < 2; j++) {
                wmma::load_matrix_sync(bh[j], &sBhi[kk][wn + 16 * j], LDB);
                wmma::load_matrix_sync(bl[j], &sBlo[kk][wn + 16 * j], LDB);
            }
#pragma unroll
            for (int i = 0; i < 2; i++)
#pragma unroll
                for (int j = 0; j < 2; j++) {
                    wmma::mma_sync(acc[i][j], ah[i], bh[j], acc[i][j]);
                    wmma::mma_sync(acc[i][j], ah[i], bl[j], acc[i][j]);
                    wmma::mma_sync(acc[i][j], al[i], bh[j], acc[i][j]);
                }
        }
        __syncthreads();
        if (t + 1 < KT) {
            store_tiles();
            __syncthreads();
        }
    }

    // ---- epilogue: leaky + store ----
#pragma unroll
    for (int i = 0; i < 2; i++)
#pragma unroll
        for (int j = 0; j < 2; j++) {
            if (leaky) {
#pragma unroll
                for (int e = 0; e < acc[i][j].num_elements; e++) {
                    float v = acc[i][j].x[e];
                    acc[i][j].x[e] = (v >= 0.f) ? v : SLOPE * v;
                }
            }
            wmma::store_matrix_sync(&C[(size_t)(bm + wm + 16 * i) * N + bn + wn + 16 * j],
                                    acc[i][j], N, wmma::mem_row_major);
        }
}

// ============================================================
// Small GEMM: C[8192,20] = A[8192,256] @ B[256,20]
// ============================================================
__global__ __launch_bounds__(320) void gemm_w3(
    const float* __restrict__ A, const float* __restrict__ B,
    float* __restrict__ C)
{
    __shared__ float Bs[256 * 20];
    int tid = threadIdx.x;
    for (int i = tid; i < 256 * 20; i += 320) Bs[i] = B[i];
    __syncthreads();

    int ty = tid / 20;
    int n  = tid % 20;
    int m = blockIdx.x * 16 + ty;

    const float* arow = A + (size_t)m * 256;
    float acc = 0.f;
#pragma unroll 8
    for (int k = 0; k < 256; k++)
        acc += arow[k] * Bs[k * 20 + n];
    C[(size_t)m * 20 + n] = acc;
}

// ============================================================
// Decoder: out[i][j] = sigmoid(dot(Z[i], Z[j])), Z=[8192,20]
// ============================================================
__global__ __launch_bounds__(256) void decoder_kernel(
    const float* __restrict__ Z, float* __restrict__ out)
{
    __shared__ float Zr[64][21];
    __shared__ float Zc[64][21];
    int tid = threadIdx.x;
    int bm = blockIdx.y * 64;
    int bn = blockIdx.x * 64;

    for (int i = tid; i < 64 * 20; i += 256) {
        int r = i / 20, c = i % 20;
        Zr[r][c] = Z[(size_t)(bm + r) * 20 + c];
        Zc[r][c] = Z[(size_t)(bn + r) * 20 + c];
    }
    __syncthreads();

    int tx = tid & 15;
    int ty = tid >> 4;
    float acc[4][4];
#pragma unroll
    for (int i = 0; i < 4; i++)
#pragma unroll
        for (int j = 0; j < 4; j++) acc[i][j] = 0.f;

#pragma unroll
    for (int k = 0; k < 20; k++) {
        float ra[4], rb[4];
#pragma unroll
        for (int i = 0; i < 4; i++) ra[i] = Zr[ty * 4 + i][k];
#pragma unroll
        for (int j = 0; j < 4; j++) rb[j] = Zc[tx * 4 + j][k];
#pragma unroll
        for (int i = 0; i < 4; i++)
#pragma unroll
            for (int j = 0; j < 4; j++)
                acc[i][j] += ra[i] * rb[j];
    }

#pragma unroll
    for (int i = 0; i < 4; i++) {
        int m = bm + ty * 4 + i;
        float4 o;
        o.x = 1.f / (1.f + __expf(-acc[i][0]));
        o.y = 1.f / (1.f + __expf(-acc[i][1]));
        o.z = 1.f / (1.f + __expf(-acc[i][2]));
        o.w = 1.f / (1.f + __expf(-acc[i][3]));
        *reinterpret_cast<float4*>(&out[(size_t)m * N_NODES + bn + tx * 4]) = o;
    }
}

// ============================================================
// Launch
// ============================================================
extern "C" void kernel_launch(void* const* d_in, const int* in_sizes, int n_in,
                              void* d_out, int out_size)
{
    const float* x        = (const float*)d_in[0];
    const int*   adj_rows = (const int*)  d_in[1];
    const int*   adj_cols = (const int*)  d_in[2];
    const float* adj_vals = (const float*)d_in[3];
    const float* w1       = (const float*)d_in[4];
    const float* w2       = (const float*)d_in[5];
    const float* w3       = (const float*)d_in[6];
    float* out = (float*)d_out;

    // output layout (floats)
    float* z_igae = out;                                   // [8192, 20]
    float* adj    = z_igae + (size_t)N_NODES * N_Z;        // [8192, 8192]
    float* az1    = adj    + (size_t)N_NODES * N_NODES;    // [8192, 128]
    float* az2    = az1    + (size_t)N_NODES * ENC1;       // [8192, 256]
    float* az3    = az2    + (size_t)N_NODES * ENC2;       // [8192, 20]
    float* z1     = az3    + (size_t)N_NODES * N_Z;        // [8192, 128]
    float* z2     = z1     + (size_t)N_NODES * ENC1;       // [8192, 256]

    float *s1, *s2, *s3, *eval;
    int *cnt, *off, *pos, *ecol;
    cudaGetSymbolAddress((void**)&s1, g_s1);
    cudaGetSymbolAddress((void**)&s2, g_s2);
    cudaGetSymbolAddress((void**)&s3, g_s3);
    cudaGetSymbolAddress((void**)&cnt, g_cnt);
    cudaGetSymbolAddress((void**)&off, g_off);
    cudaGetSymbolAddress((void**)&pos, g_pos);
    cudaGetSymbolAddress((void**)&ecol, g_ecol);
    cudaGetSymbolAddress((void**)&eval, g_eval);

    cudaStream_t st = 0;

    // ---- build CSR ----
    cudaMemsetAsync(cnt, 0, (N_NODES + 1) * sizeof(int), st);
    count_kernel<<<N_EDGES / 1024, 1024, 0, st>>>(adj_rows, cnt);
    scan_kernel<<<1, 1024, 0, st>>>(cnt, off, pos);
    scatter_kernel<<<N_EDGES / 1024, 1024, 0, st>>>(adj_rows, adj_cols, adj_vals,
                                                    pos, ecol, eval);

    // ---- layer 1 ----
    {
        dim3 grid(ENC1 / GBN, N_NODES / GBM);   // (2, 64)
        gemm_tc<<<grid, 256, 0, st>>>(x, w1, s1, N_NODES, ENC1, N_INPUT, 1);
    }
    spmm_csr<ENC1><<<N_NODES, ENC1, 0, st>>>(off, ecol, eval, s1, z1);
    spmm_csr<ENC1><<<N_NODES, ENC1, 0, st>>>(off, ecol, eval, z1, az1);

    // ---- layer 2 ----
    {
        dim3 grid(ENC2 / GBN, N_NODES / GBM);   // (4, 64)
        gemm_tc<<<grid, 256, 0, st>>>(z1, w2, s2, N_NODES, ENC2, ENC1, 1);
    }
    spmm_csr<ENC2><<<N_NODES, ENC2, 0, st>>>(off, ecol, eval, s2, z2);
    spmm_csr<ENC2><<<N_NODES, ENC2, 0, st>>>(off, ecol, eval, z2, az2);

    // ---- layer 3 (no activation) ----
    gemm_w3<<<N_NODES / 16, 320, 0, st>>>(z2, w3, s3);
    spmm_csr20<<<N_NODES / 8, 256, 0, st>>>(off, ecol, eval, s3, z_igae);
    spmm_csr20<<<N_NODES / 8, 256, 0, st>>>(off, ecol, eval, z_igae, az3);

    // ---- decoder ----
    {
        dim3 grid(N_NODES / 64, N_NODES / 64);
        decoder_kernel<<<grid, 256, 0, st>>>(z_igae, adj);
    }

    (void)in_sizes; (void)n_in; (void)out_size;
}

// round 4
// speedup vs baseline: 2.1806x; 1.1475x over previous
#include <cuda_runtime.h>
#include <cuda_bf16.h>
#include <mma.h>
#include <cstdint>

using namespace nvcuda;

#define N_NODES 8192
#define N_EDGES 262144
#define N_INPUT 3000
#define ENC1 128
#define ENC2 256
#define N_Z 20
#define SLOPE 0.2f
#define KSPLIT 4
#define KCHUNK 768

// -------- scratch (no runtime allocations allowed) --------
__device__ float g_s1[N_NODES * ENC1];            // leaky(x@w1)
__device__ float g_s2[N_NODES * ENC2];            // leaky(z1@w2)
__device__ float g_s3[N_NODES * N_Z];             // z2@w3
__device__ float g_part[KSPLIT * N_NODES * ENC1]; // split-K partials for GEMM1
// CSR scratch
__device__ int   g_cnt[N_NODES + 1];
__device__ int   g_off[N_NODES + 1];
__device__ int   g_pos[N_NODES];
__device__ int   g_ecol[N_EDGES];
__device__ float g_eval[N_EDGES];

// ============================================================
// CSR build: count -> scan -> scatter
// ============================================================
__global__ __launch_bounds__(1024) void count_kernel(const int* __restrict__ rows,
                                                     int* __restrict__ cnt)
{
    int e = blockIdx.x * 1024 + threadIdx.x;
    if (e < N_EDGES) atomicAdd(&cnt[rows[e]], 1);
}

__global__ __launch_bounds__(1024) void scan_kernel(const int* __restrict__ cnt,
                                                    int* __restrict__ off,
                                                    int* __restrict__ pos)
{
    __shared__ int wsum[32];
    int tid = threadIdx.x;
    int base = tid * 8;
    int v[8];
    int s = 0;
#pragma unroll
    for (int i = 0; i < 8; i++) { v[i] = cnt[base + i]; s += v[i]; }
    int lane = tid & 31, warp = tid >> 5;
    int inc = s;
#pragma unroll
    for (int d = 1; d < 32; d <<= 1) {
        int t = __shfl_up_sync(0xffffffff, inc, d);
        if (lane >= d) inc += t;
    }
    if (lane == 31) wsum[warp] = inc;
    __syncthreads();
    if (warp == 0) {
        int w = wsum[lane];
        int wi = w;
#pragma unroll
        for (int d = 1; d < 32; d <<= 1) {
            int t = __shfl_up_sync(0xffffffff, wi, d);
            if (lane >= d) wi += t;
        }
        wsum[lane] = wi - w;
    }
    __syncthreads();
    int run = wsum[warp] + (inc - s);
#pragma unroll
    for (int i = 0; i < 8; i++) {
        off[base + i] = run;
        pos[base + i] = run;
        run += v[i];
    }
    if (tid == 1023) off[N_NODES] = run;
}

__global__ __launch_bounds__(1024) void scatter_kernel(
    const int* __restrict__ rows, const int* __restrict__ cols,
    const float* __restrict__ vals, int* __restrict__ pos,
    int* __restrict__ ecol, float* __restrict__ eval)
{
    int e = blockIdx.x * 1024 + threadIdx.x;
    if (e >= N_EDGES) return;
    int r = rows[e];
    int idx = atomicAdd(&pos[r], 1);
    ecol[idx] = cols[e];
    eval[idx] = vals[e];
}

// ============================================================
// CSR SpMM: one CTA per node, D threads, register accumulate.
// ============================================================
template <int D>
__global__ __launch_bounds__(D) void spmm_csr(
    const int* __restrict__ off, const int* __restrict__ ecol,
    const float* __restrict__ eval, const float* __restrict__ feat,
    float* __restrict__ out)
{
    int node = blockIdx.x;
    int tid = threadIdx.x;
    int s = off[node], e = off[node + 1];
    float acc = 0.f;
    int i = s;
    for (; i + 4 <= e; i += 4) {
        int c0 = ecol[i], c1 = ecol[i + 1], c2 = ecol[i + 2], c3 = ecol[i + 3];
        float v0 = eval[i], v1 = eval[i + 1], v2 = eval[i + 2], v3 = eval[i + 3];
        float f0 = feat[(size_t)c0 * D + tid];
        float f1 = feat[(size_t)c1 * D + tid];
        float f2 = feat[(size_t)c2 * D + tid];
        float f3 = feat[(size_t)c3 * D + tid];
        acc += v0 * f0; acc += v1 * f1; acc += v2 * f2; acc += v3 * f3;
    }
    for (; i < e; i++) acc += eval[i] * feat[(size_t)ecol[i] * D + tid];
    out[(size_t)node * D + tid] = acc;
}

// D=20 variant: one warp per node (lanes 0..19 active)
__global__ __launch_bounds__(256) void spmm_csr20(
    const int* __restrict__ off, const int* __restrict__ ecol,
    const float* __restrict__ eval, const float* __restrict__ feat,
    float* __restrict__ out)
{
    int warp = (blockIdx.x * 256 + threadIdx.x) >> 5;
    int lane = threadIdx.x & 31;
    if (warp >= N_NODES || lane >= N_Z) return;
    int s = off[warp], e = off[warp + 1];
    float acc = 0.f;
    int i = s;
    for (; i + 2 <= e; i += 2) {
        int c0 = ecol[i], c1 = ecol[i + 1];
        float v0 = eval[i], v1 = eval[i + 1];
        acc += v0 * feat[(size_t)c0 * N_Z + lane];
        acc += v1 * feat[(size_t)c1 * N_Z + lane];
    }
    for (; i < e; i++) acc += eval[i] * feat[(size_t)ecol[i] * N_Z + lane];
    out[(size_t)warp * N_Z + lane] = acc;
}

// ============================================================
// Tensor-core GEMM, fused fp32 -> bf16 (hi,lo) split, split-K,
// double-buffered smem.
// acc += Ahi*Bhi + Ahi*Blo + Alo*Bhi  (error ~2^-17)
// BM=64, BN=64, BK=32; 128 threads = 4 warps (2x2), 32x32/warp.
// gridDim.z = number of K splits; each split z covers
// [z*kchunk, min(K,(z+1)*kchunk)) and writes C + z*M*N.
// If gridDim.z == 1 and leaky, apply LeakyReLU in epilogue.
// Requires M%64==0, N%64==0, K%4==0, kchunk%32==0.
// ============================================================
#define TBM 64
#define TBN 64
#define TBK 32
#define TLDA 40   // 32 + 8 pad -> conflict-free ldmatrix
#define TLDB 72   // 64 + 8 pad

__device__ __forceinline__ uint32_t pack_hi2(float a, float b) {
    __nv_bfloat162 p;
    p.x = __float2bfloat16(a);
    p.y = __float2bfloat16(b);
    return *reinterpret_cast<uint32_t*>(&p);
}
__device__ __forceinline__ uint32_t pack_lo2(float a, float b) {
    __nv_bfloat162 p;
    p.x = __float2bfloat16(a - __bfloat162float(__float2bfloat16(a)));
    p.y = __float2bfloat16(b - __bfloat162float(__float2bfloat16(b)));
    return *reinterpret_cast<uint32_t*>(&p);
}

__global__ __launch_bounds__(128) void gemm_tc(
    const float* __restrict__ A, const float* __restrict__ B,
    float* __restrict__ C, int M, int N, int K, int kchunk, int leaky)
{
    __shared__ __nv_bfloat16 sAhi[2][TBM][TLDA];
    __shared__ __nv_bfloat16 sAlo[2][TBM][TLDA];
    __shared__ __nv_bfloat16 sBhi[2][TBK][TLDB];
    __shared__ __nv_bfloat16 sBlo[2][TBK][TLDB];

    const int tid = threadIdx.x;
    const int bm = blockIdx.y * TBM;
    const int bn = blockIdx.x * TBN;
    const int kbeg = blockIdx.z * kchunk;
    const int kend = min(K, kbeg + kchunk);
    float* Cout = C + (size_t)blockIdx.z * M * N;

    const int wid = tid >> 5;
    const int wm = (wid & 1) * 32;
    const int wn = (wid >> 1) * 32;

    wmma::fragment<wmma::accumulator, 16, 16, 16, float> acc[2][2];
#pragma unroll
    for (int i = 0; i < 2; i++)
#pragma unroll
        for (int j = 0; j < 2; j++) wmma::fill_fragment(acc[i][j], 0.f);

    const int KT = (kend - kbeg + TBK - 1) / TBK;

    // A tile: 64x32 = 512 float4, 4 per thread
    // B tile: 32x64 = 512 float4, 4 per thread
    float4 ra[4], rb[4];

    auto load_regs = [&](int t) {
        int k0 = kbeg + t * TBK;
#pragma unroll
        for (int l = 0; l < 4; l++) {
            int lin = tid + l * 128;
            int row = lin >> 3;
            int c4  = (lin & 7) * 4;
            int gk = k0 + c4;
            float4 v = make_float4(0.f, 0.f, 0.f, 0.f);
            if (gk < kend)     // gk%4==0, kend%4==0 -> full vec in-bounds
                v = *reinterpret_cast<const float4*>(&A[(size_t)(bm + row) * K + gk]);
            ra[l] = v;
        }
#pragma unroll
        for (int l = 0; l < 4; l++) {
            int lin = tid + l * 128;
            int krow = lin >> 4;
            int c4 = (lin & 15) * 4;
            int gk = k0 + krow;
            float4 v = make_float4(0.f, 0.f, 0.f, 0.f);
            if (gk < kend)
                v = *reinterpret_cast<const float4*>(&B[(size_t)gk * N + bn + c4]);
            rb[l] = v;
        }
    };

    auto store_tiles = [&](int b) {
#pragma unroll
        for (int l = 0; l < 4; l++) {
            int lin = tid + l * 128;
            int row = lin >> 3;
            int c4  = (lin & 7) * 4;
            uint32_t h0 = pack_hi2(ra[l].x, ra[l].y);
            uint32_t h1 = pack_hi2(ra[l].z, ra[l].w);
            uint32_t l0 = pack_lo2(ra[l].x, ra[l].y);
            uint32_t l1 = pack_lo2(ra[l].z, ra[l].w);
            uint2* dh = reinterpret_cast<uint2*>(&sAhi[b][row][c4]);
            uint2* dl = reinterpret_cast<uint2*>(&sAlo[b][row][c4]);
            *dh = make_uint2(h0, h1);
            *dl = make_uint2(l0, l1);
        }
#pragma unroll
        for (int l = 0; l < 4; l++) {
            int lin = tid + l * 128;
            int krow = lin >> 4;
            int c4 = (lin & 15) * 4;
            uint32_t h0 = pack_hi2(rb[l].x, rb[l].y);
            uint32_t h1 = pack_hi2(rb[l].z, rb[l].w);
            uint32_t l0 = pack_lo2(rb[l].x, rb[l].y);
            uint32_t l1 = pack_lo2(rb[l].z, rb[l].w);
            uint2* dh = reinterpret_cast<uint2*>(&sBhi[b][krow][c4]);
            uint2* dl = reinterpret_cast<uint2*>(&sBlo[b][krow][c4]);
            *dh = make_uint2(h0, h1);
            *dl = make_uint2(l0, l1);
        }
    };

    load_regs(0);
    store_tiles(0);
    __syncthreads();

    for (int t = 0; t < KT; t++) {
        int buf = t & 1;
        if (t + 1 < KT) load_regs(t + 1);   // LDG overlaps MMAs below

#pragma unroll
        for (int kk = 0; kk < TBK; kk += 16) {
            wmma::fragment<wmma::matrix_a, 16, 16, 16, __nv_bfloat16, wmma::row_major> ah[2], al[2];
            wmma::fragment<wmma::matrix_b, 16, 16, 16, __nv_bfloat16, wmma::row_major> bh[2], bl[2];
#pragma unroll
            for (int i = 0; i < 2; i++) {
                wmma::load_matrix_sync(ah[i], &sAhi[buf][wm + 16 * i][kk], TLDA);
                wmma::load_matrix_sync(al[i], &sAlo[buf][wm + 16 * i][kk], TLDA);
            }
#pragma unroll
            for (int j = 0; j < 2; j++) {
                wmma::load_matrix_sync(bh[j], &sBhi[buf][kk][wn + 16 * j], TLDB);
                wmma::load_matrix_sync(bl[j], &sBlo[buf][kk][wn + 16 * j], TLDB);
            }
#pragma unroll
            for (int i = 0; i < 2; i++)
#pragma unroll
                for (int j = 0; j < 2; j++) {
                    wmma::mma_sync(acc[i][j], ah[i], bh[j], acc[i][j]);
                    wmma::mma_sync(acc[i][j], ah[i], bl[j], acc[i][j]);
                    wmma::mma_sync(acc[i][j], al[i], bh[j], acc[i][j]);
                }
        }
        if (t + 1 < KT) store_tiles(1 - buf);  // other buffer: safe pre-sync
        __syncthreads();
    }

    // ---- epilogue ----
#pragma unroll
    for (int i = 0; i < 2; i++)
#pragma unroll
        for (int j = 0; j < 2; j++) {
            if (leaky) {
#pragma unroll
                for (int e = 0; e < acc[i][j].num_elements; e++) {
                    float v = acc[i][j].x[e];
                    acc[i][j].x[e] = (v >= 0.f) ? v : SLOPE * v;
                }
            }
            wmma::store_matrix_sync(&Cout[(size_t)(bm + wm + 16 * i) * N + bn + wn + 16 * j],
                                    acc[i][j], N, wmma::mem_row_major);
        }
}

// ============================================================
// Reduce KSPLIT partials + LeakyReLU -> s1 (float4 granularity)
// ============================================================
__global__ __launch_bounds__(256) void reduce_leaky(const float4* __restrict__ p,
                                                    float4* __restrict__ out)
{
    const int stride = N_NODES * ENC1 / 4;
    int i = blockIdx.x * 256 + threadIdx.x;
    float4 a = p[i];
    float4 b = p[i + stride];
    float4 c = p[i + 2 * stride];
    float4 d = p[i + 3 * stride];
    float4 r;
    r.x = a.x + b.x + c.x + d.x;
    r.y = a.y + b.y + c.y + d.y;
    r.z = a.z + b.z + c.z + d.z;
    r.w = a.w + b.w + c.w + d.w;
    r.x = (r.x >= 0.f) ? r.x : SLOPE * r.x;
    r.y = (r.y >= 0.f) ? r.y : SLOPE * r.y;
    r.z = (r.z >= 0.f) ? r.z : SLOPE * r.z;
    r.w = (r.w >= 0.f) ? r.w : SLOPE * r.w;
    out[i] = r;
}

// ============================================================
// Small GEMM: C[8192,20] = A[8192,256] @ B[256,20]
// ============================================================
__global__ __launch_bounds__(320) void gemm_w3(
    const float* __restrict__ A, const float* __restrict__ B,
    float* __restrict__ C)
{
    __shared__ float Bs[256 * 20];
    int tid = threadIdx.x;
    for (int i = tid; i < 256 * 20; i += 320) Bs[i] = B[i];
    __syncthreads();

    int ty = tid / 20;
    int n  = tid % 20;
    int m = blockIdx.x * 16 + ty;

    const float* arow = A + (size_t)m * 256;
    float acc = 0.f;
#pragma unroll 8
    for (int k = 0; k < 256; k++)
        acc += arow[k] * Bs[k * 20 + n];
    C[(size_t)m * 20 + n] = acc;
}

// ============================================================
// Decoder: out[i][j] = sigmoid(dot(Z[i], Z[j])), Z=[8192,20]
// ============================================================
__global__ __launch_bounds__(256) void decoder_kernel(
    const float* __restrict__ Z, float* __restrict__ out)
{
    __shared__ float Zr[64][21];
    __shared__ float Zc[64][21];
    int tid = threadIdx.x;
    int bm = blockIdx.y * 64;
    int bn = blockIdx.x * 64;

    for (int i = tid; i < 64 * 20; i += 256) {
        int r = i / 20, c = i % 20;
        Zr[r][c] = Z[(size_t)(bm + r) * 20 + c];
        Zc[r][c] = Z[(size_t)(bn + r) * 20 + c];
    }
    __syncthreads();

    int tx = tid & 15;
    int ty = tid >> 4;
    float acc[4][4];
#pragma unroll
    for (int i = 0; i < 4; i++)
#pragma unroll
        for (int j = 0; j < 4; j++) acc[i][j] = 0.f;

#pragma unroll
    for (int k = 0; k < 20; k++) {
        float ra[4], rb[4];
#pragma unroll
        for (int i = 0; i < 4; i++) ra[i] = Zr[ty * 4 + i][k];
#pragma unroll
        for (int j = 0; j < 4; j++) rb[j] = Zc[tx * 4 + j][k];
#pragma unroll
        for (int i = 0; i < 4; i++)
#pragma unroll
            for (int j = 0; j < 4; j++)
                acc[i][j] += ra[i] * rb[j];
    }

#pragma unroll
    for (int i = 0; i < 4; i++) {
        int m = bm + ty * 4 + i;
        float4 o;
        o.x = 1.f / (1.f + __expf(-acc[i][0]));
        o.y = 1.f / (1.f + __expf(-acc[i][1]));
        o.z = 1.f / (1.f + __expf(-acc[i][2]));
        o.w = 1.f / (1.f + __expf(-acc[i][3]));
        *reinterpret_cast<float4*>(&out[(size_t)m * N_NODES + bn + tx * 4]) = o;
    }
}

// ============================================================
// Launch
// ============================================================
extern "C" void kernel_launch(void* const* d_in, const int* in_sizes, int n_in,
                              void* d_out, int out_size)
{
    const float* x        = (const float*)d_in[0];
    const int*   adj_rows = (const int*)  d_in[1];
    const int*   adj_cols = (const int*)  d_in[2];
    const float* adj_vals = (const float*)d_in[3];
    const float* w1       = (const float*)d_in[4];
    const float* w2       = (const float*)d_in[5];
    const float* w3       = (const float*)d_in[6];
    float* out = (float*)d_out;

    // output layout (floats)
    float* z_igae = out;                                   // [8192, 20]
    float* adj    = z_igae + (size_t)N_NODES * N_Z;        // [8192, 8192]
    float* az1    = adj    + (size_t)N_NODES * N_NODES;    // [8192, 128]
    float* az2    = az1    + (size_t)N_NODES * ENC1;       // [8192, 256]
    float* az3    = az2    + (size_t)N_NODES * ENC2;       // [8192, 20]
    float* z1     = az3    + (size_t)N_NODES * N_Z;        // [8192, 128]
    float* z2     = z1     + (size_t)N_NODES * ENC1;       // [8192, 256]

    float *s1, *s2, *s3, *eval, *part;
    int *cnt, *off, *pos, *ecol;
    cudaGetSymbolAddress((void**)&s1, g_s1);
    cudaGetSymbolAddress((void**)&s2, g_s2);
    cudaGetSymbolAddress((void**)&s3, g_s3);
    cudaGetSymbolAddress((void**)&part, g_part);
    cudaGetSymbolAddress((void**)&cnt, g_cnt);
    cudaGetSymbolAddress((void**)&off, g_off);
    cudaGetSymbolAddress((void**)&pos, g_pos);
    cudaGetSymbolAddress((void**)&ecol, g_ecol);
    cudaGetSymbolAddress((void**)&eval, g_eval);

    cudaStream_t st = 0;

    // ---- build CSR ----
    cudaMemsetAsync(cnt, 0, (N_NODES + 1) * sizeof(int), st);
    count_kernel<<<N_EDGES / 1024, 1024, 0, st>>>(adj_rows, cnt);
    scan_kernel<<<1, 1024, 0, st>>>(cnt, off, pos);
    scatter_kernel<<<N_EDGES / 1024, 1024, 0, st>>>(adj_rows, adj_cols, adj_vals,
                                                    pos, ecol, eval);

    // ---- layer 1: split-K GEMM + reduce-leaky ----
    {
        dim3 grid(ENC1 / TBN, N_NODES / TBM, KSPLIT);   // (2, 128, 4)
        gemm_tc<<<grid, 128, 0, st>>>(x, w1, part, N_NODES, ENC1, N_INPUT, KCHUNK, 0);
        reduce_leaky<<<(N_NODES * ENC1 / 4) / 256, 256, 0, st>>>(
            (const float4*)part, (float4*)s1);
    }
    spmm_csr<ENC1><<<N_NODES, ENC1, 0, st>>>(off, ecol, eval, s1, z1);
    spmm_csr<ENC1><<<N_NODES, ENC1, 0, st>>>(off, ecol, eval, z1, az1);

    // ---- layer 2 ----
    {
        dim3 grid(ENC2 / TBN, N_NODES / TBM, 1);        // (4, 128)
        gemm_tc<<<grid, 128, 0, st>>>(z1, w2, s2, N_NODES, ENC2, ENC1, ENC1, 1);
    }
    spmm_csr<ENC2><<<N_NODES, ENC2, 0, st>>>(off, ecol, eval, s2, z2);
    spmm_csr<ENC2><<<N_NODES, ENC2, 0, st>>>(off, ecol, eval, z2, az2);

    // ---- layer 3 (no activation) ----
    gemm_w3<<<N_NODES / 16, 320, 0, st>>>(z2, w3, s3);
    spmm_csr20<<<N_NODES / 8, 256, 0, st>>>(off, ecol, eval, s3, z_igae);
    spmm_csr20<<<N_NODES / 8, 256, 0, st>>>(off, ecol, eval, z_igae, az3);

    // ---- decoder ----
    {
        dim3 grid(N_NODES / 64, N_NODES / 64);
        decoder_kernel<<<grid, 256, 0, st>>>(z_igae, adj);
    }

    (void)in_sizes; (void)n_in; (void)out_size;
}